// round 4
// baseline (speedup 1.0000x reference)
#include <cuda_runtime.h>
#include <math.h>

// CapsuleLayer dynamic routing, fully fused.
//   x: (4, 256, 14, 14) f32      weight: (32, 288, 8, 16) f32
//   out: (4, 512, 12, 12) f32
// One CTA = (output capsule o, 4 adjacent ow positions at fixed b,oh).
// 288 threads; thread k = kk*32+inc owns route k: computes prior[k][0..15]
// for all 4 positions in registers, then runs 3 routing iterations with
// block reductions. Priors never touch memory.

#define GPOS 4          // ow positions per CTA
#define NTHR 288
#define NWARP 9

__global__ __launch_bounds__(NTHR, 2)
void caps_route_kernel(const float* __restrict__ x,
                       const float* __restrict__ w,
                       float* __restrict__ out)
{
    // s_x[(kh*6 + ww)*256 + i*32 + inc] = x[b][inc*8+i][oh+kh][ow0+ww]
    __shared__ float s_x[3 * 6 * 256];        // 18 KB
    __shared__ float s_part[NWARP * 16];
    __shared__ float s_red[16];
    __shared__ float s_sc[NWARP];

    const int tid  = threadIdx.x;
    const int lane = tid & 31;
    const int wid  = tid >> 5;            // warp id == kk (0..8)
    const int kk   = wid;
    const int inc  = lane;
    const int kh   = kk / 3;
    const int kw   = kk - 3 * kh;

    const int nb  = blockIdx.x;           // 0..143 : (b, oh, ow-group)
    const int o   = blockIdx.y;           // 0..31
    const int b   = nb / 36;
    const int r   = nb - b * 36;
    const int oh  = r / 3;
    const int ow0 = (r - oh * 3) * GPOS;

    // ---- stage x patch: 3 x 6 x 256 floats, coalesced-ish read, permuted write
    {
        const float* xb = x + (size_t)b * 256 * 14 * 14;
        for (int e = tid; e < 3 * 6 * 256; e += NTHR) {
            int c   = e / 18;
            int rr  = e - c * 18;
            int khh = rr / 6;
            int ww  = rr - khh * 6;
            float val = xb[(c * 14 + oh + khh) * 14 + ow0 + ww];
            int i  = c & 7;
            int ic = c >> 3;
            s_x[(khh * 6 + ww) * 256 + i * 32 + ic] = val;
        }
    }
    __syncthreads();

    // ---- compute priors: pr[g][c] = sum_i x_tile[g][k][i] * w[o][k][i][c]
    float pr[GPOS][16];
#pragma unroll
    for (int g = 0; g < GPOS; ++g)
#pragma unroll
        for (int c = 0; c < 16; ++c) pr[g][c] = 0.0f;

    const float4* wk = (const float4*)(w + ((size_t)o * 288 + tid) * 8 * 16);
#pragma unroll
    for (int i = 0; i < 8; ++i) {
        float4 q0 = wk[i * 4 + 0];
        float4 q1 = wk[i * 4 + 1];
        float4 q2 = wk[i * 4 + 2];
        float4 q3 = wk[i * 4 + 3];
        float wv[16];
        wv[0]=q0.x; wv[1]=q0.y; wv[2]=q0.z; wv[3]=q0.w;
        wv[4]=q1.x; wv[5]=q1.y; wv[6]=q1.z; wv[7]=q1.w;
        wv[8]=q2.x; wv[9]=q2.y; wv[10]=q2.z; wv[11]=q2.w;
        wv[12]=q3.x; wv[13]=q3.y; wv[14]=q3.z; wv[15]=q3.w;
        const float* sx = &s_x[(kh * 6 + kw) * 256 + i * 32 + inc];
#pragma unroll
        for (int g = 0; g < GPOS; ++g) {
            float t = sx[g * 256];       // conflict-free: lane = inc
#pragma unroll
            for (int c = 0; c < 16; ++c) pr[g][c] = fmaf(t, wv[c], pr[g][c]);
        }
    }

    // ---- dynamic routing per position g (all 288 threads participate)
#pragma unroll
    for (int g = 0; g < GPOS; ++g) {
        float logit = 0.0f;
        float scale = 0.0f;

#pragma unroll
        for (int it = 0; it < 3; ++it) {
            float p;
            if (it == 0) {
                p = 1.0f / 288.0f;       // softmax of zeros
            } else {
                // block max over 288 logits
                float m = logit;
#pragma unroll
                for (int off = 16; off; off >>= 1)
                    m = fmaxf(m, __shfl_xor_sync(0xffffffffu, m, off));
                __syncthreads();
                if (lane == 0) s_sc[wid] = m;
                __syncthreads();
                m = s_sc[0];
#pragma unroll
                for (int ww = 1; ww < NWARP; ++ww) m = fmaxf(m, s_sc[ww]);

                float e = __expf(logit - m);
                float Z = e;
#pragma unroll
                for (int off = 16; off; off >>= 1)
                    Z += __shfl_xor_sync(0xffffffffu, Z, off);
                __syncthreads();            // protect prior s_sc reads
                if (lane == 0) s_sc[wid] = Z;
                __syncthreads();
                Z = 0.0f;
#pragma unroll
                for (int ww = 0; ww < NWARP; ++ww) Z += s_sc[ww];
                p = e / Z;
            }

            // s[c] = sum_k p_k * pr[k][c]  — warp shuffle + 9-warp combine
            float y[16];
#pragma unroll
            for (int c = 0; c < 16; ++c) y[c] = p * pr[g][c];
#pragma unroll
            for (int off = 16; off; off >>= 1)
#pragma unroll
                for (int c = 0; c < 16; ++c)
                    y[c] += __shfl_xor_sync(0xffffffffu, y[c], off);
            __syncthreads();                // protect prior s_part/s_red reads
            if (lane == 0) {
#pragma unroll
                for (int c = 0; c < 16; ++c) s_part[wid * 16 + c] = y[c];
            }
            __syncthreads();
            if (tid < 16) {
                float a = 0.0f;
#pragma unroll
                for (int ww = 0; ww < NWARP; ++ww) a += s_part[ww * 16 + tid];
                s_red[tid] = a;
            }
            __syncthreads();

            // squash: v = s * sqrt(sq)/(1+sq); fold into scalar 'scale'
            float sr[16];
            float sq = 0.0f;
#pragma unroll
            for (int c = 0; c < 16; ++c) { sr[c] = s_red[c]; sq = fmaf(sr[c], sr[c], sq); }
            scale = sqrtf(sq) / (1.0f + sq);

            if (it < 2) {
                float d = 0.0f;
#pragma unroll
                for (int c = 0; c < 16; ++c) d = fmaf(pr[g][c], sr[c], d);
                logit += scale * d;         // logit update with v = scale * s
            }
        }

        // write output: out[b][o*16+c][oh][ow0+g]
        if (tid < 16) {
            out[(((size_t)b * 512 + o * 16 + tid) * 12 + oh) * 12 + (ow0 + g)]
                = s_red[tid] * scale;
        }
        __syncthreads();                    // s_red/s_part reuse by next g
    }
}

extern "C" void kernel_launch(void* const* d_in, const int* in_sizes, int n_in,
                              void* d_out, int out_size)
{
    const float* x = (const float*)d_in[0];
    const float* w = (const float*)d_in[1];
    // metadata order is (x, weight); swap defensively by element count
    if (n_in >= 2 && in_sizes[0] == 32 * 288 * 8 * 16 && in_sizes[1] == 4 * 256 * 14 * 14) {
        x = (const float*)d_in[1];
        w = (const float*)d_in[0];
    }
    dim3 grid(144, 32);   // (b,oh,ow-group) x out-capsule
    caps_route_kernel<<<grid, NTHR>>>(x, w, (float*)d_out);
}

// round 5
// speedup vs baseline: 1.0020x; 1.0020x over previous
#include <cuda_runtime.h>
#include <math.h>

// CapsuleLayer dynamic routing, fully fused.
//   x: (4, 256, 14, 14) f32      weight: (32, 288, 8, 16) f32
//   out: (4, 512, 12, 12) f32
// One CTA = (output capsule o, 4 adjacent ow positions at fixed b,oh).
// 288 threads; thread k = kk*32+inc owns route k: computes prior[k][0..15]
// for all 4 positions in registers, then runs 3 routing iterations with
// block reductions. Priors never touch memory.

#define GPOS 4          // ow positions per CTA
#define NTHR 288
#define NWARP 9

__global__ __launch_bounds__(NTHR, 2)
void caps_route_kernel(const float* __restrict__ x,
                       const float* __restrict__ w,
                       float* __restrict__ out)
{
    // s_x[(kh*6 + ww)*256 + i*32 + inc] = x[b][inc*8+i][oh+kh][ow0+ww]
    __shared__ float s_x[3 * 6 * 256];        // 18 KB
    __shared__ float s_part[NWARP * 16];
    __shared__ float s_red[16];
    __shared__ float s_sc[NWARP];

    const int tid  = threadIdx.x;
    const int lane = tid & 31;
    const int wid  = tid >> 5;            // warp id == kk (0..8)
    const int kk   = wid;
    const int inc  = lane;
    const int kh   = kk / 3;
    const int kw   = kk - 3 * kh;

    const int nb  = blockIdx.x;           // 0..143 : (b, oh, ow-group)
    const int o   = blockIdx.y;           // 0..31
    const int b   = nb / 36;
    const int r   = nb - b * 36;
    const int oh  = r / 3;
    const int ow0 = (r - oh * 3) * GPOS;

    // ---- stage x patch: 3 x 6 x 256 floats, coalesced-ish read, permuted write
    {
        const float* xb = x + (size_t)b * 256 * 14 * 14;
        for (int e = tid; e < 3 * 6 * 256; e += NTHR) {
            int c   = e / 18;
            int rr  = e - c * 18;
            int khh = rr / 6;
            int ww  = rr - khh * 6;
            float val = xb[(c * 14 + oh + khh) * 14 + ow0 + ww];
            int i  = c & 7;
            int ic = c >> 3;
            s_x[(khh * 6 + ww) * 256 + i * 32 + ic] = val;
        }
    }
    __syncthreads();

    // ---- compute priors: pr[g][c] = sum_i x_tile[g][k][i] * w[o][k][i][c]
    float pr[GPOS][16];
#pragma unroll
    for (int g = 0; g < GPOS; ++g)
#pragma unroll
        for (int c = 0; c < 16; ++c) pr[g][c] = 0.0f;

    const float4* wk = (const float4*)(w + ((size_t)o * 288 + tid) * 8 * 16);
#pragma unroll
    for (int i = 0; i < 8; ++i) {
        float4 q0 = wk[i * 4 + 0];
        float4 q1 = wk[i * 4 + 1];
        float4 q2 = wk[i * 4 + 2];
        float4 q3 = wk[i * 4 + 3];
        float wv[16];
        wv[0]=q0.x; wv[1]=q0.y; wv[2]=q0.z; wv[3]=q0.w;
        wv[4]=q1.x; wv[5]=q1.y; wv[6]=q1.z; wv[7]=q1.w;
        wv[8]=q2.x; wv[9]=q2.y; wv[10]=q2.z; wv[11]=q2.w;
        wv[12]=q3.x; wv[13]=q3.y; wv[14]=q3.z; wv[15]=q3.w;
        const float* sx = &s_x[(kh * 6 + kw) * 256 + i * 32 + inc];
#pragma unroll
        for (int g = 0; g < GPOS; ++g) {
            float t = sx[g * 256];       // conflict-free: lane = inc
#pragma unroll
            for (int c = 0; c < 16; ++c) pr[g][c] = fmaf(t, wv[c], pr[g][c]);
        }
    }

    // ---- dynamic routing per position g (all 288 threads participate)
#pragma unroll
    for (int g = 0; g < GPOS; ++g) {
        float logit = 0.0f;
        float scale = 0.0f;

#pragma unroll
        for (int it = 0; it < 3; ++it) {
            float p;
            if (it == 0) {
                p = 1.0f / 288.0f;       // softmax of zeros
            } else {
                // block max over 288 logits
                float m = logit;
#pragma unroll
                for (int off = 16; off; off >>= 1)
                    m = fmaxf(m, __shfl_xor_sync(0xffffffffu, m, off));
                __syncthreads();
                if (lane == 0) s_sc[wid] = m;
                __syncthreads();
                m = s_sc[0];
#pragma unroll
                for (int ww = 1; ww < NWARP; ++ww) m = fmaxf(m, s_sc[ww]);

                float e = __expf(logit - m);
                float Z = e;
#pragma unroll
                for (int off = 16; off; off >>= 1)
                    Z += __shfl_xor_sync(0xffffffffu, Z, off);
                __syncthreads();            // protect prior s_sc reads
                if (lane == 0) s_sc[wid] = Z;
                __syncthreads();
                Z = 0.0f;
#pragma unroll
                for (int ww = 0; ww < NWARP; ++ww) Z += s_sc[ww];
                p = e / Z;
            }

            // s[c] = sum_k p_k * pr[k][c]  — warp shuffle + 9-warp combine
            float y[16];
#pragma unroll
            for (int c = 0; c < 16; ++c) y[c] = p * pr[g][c];
#pragma unroll
            for (int off = 16; off; off >>= 1)
#pragma unroll
                for (int c = 0; c < 16; ++c)
                    y[c] += __shfl_xor_sync(0xffffffffu, y[c], off);
            __syncthreads();                // protect prior s_part/s_red reads
            if (lane == 0) {
#pragma unroll
                for (int c = 0; c < 16; ++c) s_part[wid * 16 + c] = y[c];
            }
            __syncthreads();
            if (tid < 16) {
                float a = 0.0f;
#pragma unroll
                for (int ww = 0; ww < NWARP; ++ww) a += s_part[ww * 16 + tid];
                s_red[tid] = a;
            }
            __syncthreads();

            // squash: v = s * sqrt(sq)/(1+sq); fold into scalar 'scale'
            float sr[16];
            float sq = 0.0f;
#pragma unroll
            for (int c = 0; c < 16; ++c) { sr[c] = s_red[c]; sq = fmaf(sr[c], sr[c], sq); }
            scale = sqrtf(sq) / (1.0f + sq);

            if (it < 2) {
                float d = 0.0f;
#pragma unroll
                for (int c = 0; c < 16; ++c) d = fmaf(pr[g][c], sr[c], d);
                logit += scale * d;         // logit update with v = scale * s
            }
        }

        // write output: out[b][o*16+c][oh][ow0+g]
        if (tid < 16) {
            out[(((size_t)b * 512 + o * 16 + tid) * 12 + oh) * 12 + (ow0 + g)]
                = s_red[tid] * scale;
        }
        __syncthreads();                    // s_red/s_part reuse by next g
    }
}

extern "C" void kernel_launch(void* const* d_in, const int* in_sizes, int n_in,
                              void* d_out, int out_size)
{
    const float* x = (const float*)d_in[0];
    const float* w = (const float*)d_in[1];
    // metadata order is (x, weight); swap defensively by element count
    if (n_in >= 2 && in_sizes[0] == 32 * 288 * 8 * 16 && in_sizes[1] == 4 * 256 * 14 * 14) {
        x = (const float*)d_in[1];
        w = (const float*)d_in[0];
    }
    dim3 grid(144, 32);   // (b,oh,ow-group) x out-capsule
    caps_route_kernel<<<grid, NTHR>>>(x, w, (float*)d_out);
}

// round 6
// speedup vs baseline: 1.2200x; 1.2176x over previous
#include <cuda_runtime.h>
#include <math.h>

// CapsuleLayer dynamic routing, fully fused.
//   x: (4, 256, 14, 14) f32   weight: (32, 288, 8, 16) f32   out: (4, 512, 12, 12) f32
// One CTA = (out capsule o, 4 adjacent ow at fixed b,oh). 288 threads; thread k
// owns route k: priors pr[4][16] live in registers. Weights are staged through
// SMEM in i-pair chunks with perfectly coalesced LDG and XOR-swizzled,
// conflict-free STS/LDS. Routing reductions use a 16-shuffle reduce-scatter.

#define GPOS 4
#define NTHR 288
#define NWARP 9

__global__ __launch_bounds__(NTHR, 2)
void caps_route_kernel(const float* __restrict__ x,
                       const float* __restrict__ w,
                       float* __restrict__ out)
{
    __shared__ float  s_x[3 * 6 * 256];      // 18 KB : [kh*6+w][i*32+inc]
    __shared__ float4 s_w4[288 * 8];         // 36 KB : swizzled i-pair chunk
    __shared__ float  s_part[NWARP * 16];
    __shared__ float  s_red[16];
    __shared__ float  s_sc[NWARP];
    __shared__ float  s_out[16 * GPOS];

    const int tid  = threadIdx.x;
    const int lane = tid & 31;
    const int wid  = tid >> 5;               // == kk (0..8)
    const int kh   = wid / 3;
    const int kw   = wid - 3 * kh;

    const int nb  = blockIdx.x;              // (b, oh, ow-group)
    const int o   = blockIdx.y;
    const int b   = nb / 36;
    const int r   = nb - b * 36;
    const int oh  = r / 3;
    const int ow0 = (r - oh * 3) * GPOS;

    // ---- stage x patch (18 KB), permuted so compute LDS is conflict-free
    {
        const float* xb = x + (size_t)b * 256 * 14 * 14;
        for (int e = tid; e < 3 * 6 * 256; e += NTHR) {
            int c   = e / 18;
            int rr  = e - c * 18;
            int khh = rr / 6;
            int ww  = rr - khh * 6;
            float val = xb[(c * 14 + oh + khh) * 14 + ow0 + ww];
            s_x[(khh * 6 + ww) * 256 + (c & 7) * 32 + (c >> 3)] = val;
        }
    }

    float pr[GPOS][16];
#pragma unroll
    for (int g = 0; g < GPOS; ++g)
#pragma unroll
        for (int c = 0; c < 16; ++c) pr[g][c] = 0.0f;

    const float4* wbase  = (const float4*)(w + (size_t)o * 288 * 128);
    const float*  sxbase = &s_x[(kh * 6 + kw) * 256 + lane];   // + i*32 + g*256

    // ---- priors: 4 chunks, each = (all k) x (i pair) = 36 KB, coalesced LDG
#pragma unroll 1
    for (int p = 0; p < 4; ++p) {
        __syncthreads();                     // x ready (p=0) / s_w4 free (p>0)
#pragma unroll
        for (int pass = 0; pass < 8; ++pass) {
            int idx = tid + pass * NTHR;     // 0..2303
            int k   = idx >> 3;
            int j   = idx & 7;
            float4 v = wbase[k * 32 + p * 8 + j];       // 128B-contig per 8 lanes
            s_w4[k * 8 + (j ^ (k & 7))] = v;            // swizzled, no conflicts
        }
        __syncthreads();
#pragma unroll
        for (int half = 0; half < 2; ++half) {
            const int i = 2 * p + half;
            float wv[16];
#pragma unroll
            for (int j = 0; j < 4; ++j) {
                float4 q = s_w4[tid * 8 + ((half * 4 + j) ^ (tid & 7))];
                wv[j * 4 + 0] = q.x; wv[j * 4 + 1] = q.y;
                wv[j * 4 + 2] = q.z; wv[j * 4 + 3] = q.w;
            }
#pragma unroll
            for (int g = 0; g < GPOS; ++g) {
                float t = sxbase[i * 32 + g * 256];     // lane==inc: no conflict
#pragma unroll
                for (int c = 0; c < 16; ++c) pr[g][c] = fmaf(t, wv[c], pr[g][c]);
            }
        }
    }

    // ---- dynamic routing per position g
#pragma unroll 1
    for (int g = 0; g < GPOS; ++g) {
        float logit = 0.0f;
        float scale = 0.0f;

#pragma unroll 1
        for (int it = 0; it < 3; ++it) {
            float p;
            if (it == 0) {
                p = 1.0f / 288.0f;
            } else {
                float m = logit;
#pragma unroll
                for (int off = 16; off; off >>= 1)
                    m = fmaxf(m, __shfl_xor_sync(0xffffffffu, m, off));
                __syncthreads();
                if (lane == 0) s_sc[wid] = m;
                __syncthreads();
                m = s_sc[0];
#pragma unroll
                for (int ww = 1; ww < NWARP; ++ww) m = fmaxf(m, s_sc[ww]);

                float e = __expf(logit - m);
                float Z = e;
#pragma unroll
                for (int off = 16; off; off >>= 1)
                    Z += __shfl_xor_sync(0xffffffffu, Z, off);
                __syncthreads();
                if (lane == 0) s_sc[wid] = Z;
                __syncthreads();
                Z = 0.0f;
#pragma unroll
                for (int ww = 0; ww < NWARP; ++ww) Z += s_sc[ww];
                p = e / Z;
            }

            // s[c] = sum_k p_k*pr[k][c] : reduce-scatter butterfly (16 shfls)
            float y[16];
#pragma unroll
            for (int c = 0; c < 16; ++c) y[c] = p * pr[g][c];
            // offset 16: keep 8
#pragma unroll
            for (int c = 0; c < 8; ++c) {
                float snd = (lane & 16) ? y[c] : y[c + 8];
                float rcv = __shfl_xor_sync(0xffffffffu, snd, 16);
                y[c] = ((lane & 16) ? y[c + 8] : y[c]) + rcv;
            }
            // offset 8: keep 4
#pragma unroll
            for (int c = 0; c < 4; ++c) {
                float snd = (lane & 8) ? y[c] : y[c + 4];
                float rcv = __shfl_xor_sync(0xffffffffu, snd, 8);
                y[c] = ((lane & 8) ? y[c + 4] : y[c]) + rcv;
            }
            // offset 4: keep 2
#pragma unroll
            for (int c = 0; c < 2; ++c) {
                float snd = (lane & 4) ? y[c] : y[c + 2];
                float rcv = __shfl_xor_sync(0xffffffffu, snd, 4);
                y[c] = ((lane & 4) ? y[c + 2] : y[c]) + rcv;
            }
            // offset 2: keep 1
            {
                float snd = (lane & 2) ? y[0] : y[1];
                float rcv = __shfl_xor_sync(0xffffffffu, snd, 2);
                y[0] = ((lane & 2) ? y[1] : y[0]) + rcv;
            }
            y[0] += __shfl_xor_sync(0xffffffffu, y[0], 1);
            // lane l now holds warp-sum of component (l>>1)&15

            __syncthreads();                       // prior s_part/s_red readers done
            if (!(lane & 1)) s_part[wid * 16 + ((lane >> 1) & 15)] = y[0];
            __syncthreads();
            if (tid < 16) {
                float a = 0.0f;
#pragma unroll
                for (int ww = 0; ww < NWARP; ++ww) a += s_part[ww * 16 + tid];
                s_red[tid] = a;
            }
            __syncthreads();

            // squash scalar + (optional) logit update in one pass over s_red
            float sq = 0.0f, d = 0.0f;
#pragma unroll
            for (int c = 0; c < 16; ++c) {
                float v = s_red[c];                // broadcast LDS
                sq = fmaf(v, v, sq);
                d  = fmaf(pr[g][c], v, d);
            }
            scale = sqrtf(sq) / (1.0f + sq);
            if (it < 2) logit += scale * d;        // outputs = scale * s
        }

        if (tid < 16) s_out[tid * GPOS + g] = s_red[tid] * scale;
        __syncthreads();
    }

    // ---- output: 64 threads write 16 rows x 4 contiguous floats
    if (tid < 16 * GPOS) {
        int c = tid >> 2;
        int g = tid & 3;
        out[(((size_t)b * 512 + o * 16 + c) * 12 + oh) * 12 + (ow0 + g)]
            = s_out[c * GPOS + g];
    }
}

extern "C" void kernel_launch(void* const* d_in, const int* in_sizes, int n_in,
                              void* d_out, int out_size)
{
    const float* x = (const float*)d_in[0];
    const float* w = (const float*)d_in[1];
    if (n_in >= 2 && in_sizes[0] == 32 * 288 * 8 * 16 && in_sizes[1] == 4 * 256 * 14 * 14) {
        x = (const float*)d_in[1];
        w = (const float*)d_in[0];
    }
    dim3 grid(144, 32);
    caps_route_kernel<<<grid, NTHR>>>(x, w, (float*)d_out);
}

// round 7
// speedup vs baseline: 1.3279x; 1.0884x over previous
#include <cuda_runtime.h>
#include <math.h>

// CapsuleLayer dynamic routing, fully fused, weight-slab resident in SMEM.
//   x: (4,256,14,14) f32   weight: (32,288,8,16) f32   out: (4,512,12,12) f32
// Grid (9,32): CTA = (chunk of 16 position-groups, output capsule o).
// 576 threads = two 288-thread halves; per iteration each half processes one
// 4-position group. Weights (147 KB) staged into SMEM ONCE per CTA with
// coalesced LDG + XOR-swizzled conflict-free STS/LDS. Thread k=htid owns
// route k: priors pr[4][16] in registers; routing via shuffle reduce-scatter.

#define GPOS 4
#define HALF_THR 288
#define NTHR 576
#define NWARP 9            // warps per half
#define GROUPS_PER_CHUNK 16
#define ITERS_PER_CTA 8    // 2 groups per iteration

__global__ __launch_bounds__(NTHR, 1)
void caps_route_kernel(const float* __restrict__ x,
                       const float* __restrict__ w,
                       float* __restrict__ out)
{
    extern __shared__ float smem[];
    float4* s_w4   = (float4*)smem;                 // 288*32 float4 = 147456 B
    float*  s_x    = smem + 288 * 32 * 4;           // 2 * 4608 floats
    float*  s_part = s_x + 2 * 4608;                // 2 * 9 * 16
    float*  s_red  = s_part + 2 * NWARP * 16;       // 2 * 16
    float*  s_sc   = s_red + 2 * 16;                // 2 * 9
    float*  s_out  = s_sc + 2 * NWARP;              // 2 * 64

    const int tid  = threadIdx.x;
    const int h    = tid / HALF_THR;                // half id (warp-aligned: 288=9*32)
    const int htid = tid - h * HALF_THR;            // 0..287, == route k
    const int lane = tid & 31;
    const int wh   = htid >> 5;                     // warp-in-half == kk (0..8)
    const int kh   = wh / 3;
    const int kw   = wh - 3 * kh;

    float* s_xh    = s_x    + h * 4608;
    float* s_parth = s_part + h * NWARP * 16;
    float* s_redh  = s_red  + h * 16;
    float* s_sch   = s_sc   + h * NWARP;
    float* s_outh  = s_out  + h * 64;

    const int o = blockIdx.y;

    // ---- stage the full weight slab for o: 147 KB, once per CTA
    {
        const float4* wbase = (const float4*)(w + (size_t)o * 288 * 128);
#pragma unroll
        for (int pass = 0; pass < 16; ++pass) {
            int idx = tid + pass * NTHR;            // 0..9215, warp = one k, j=0..31
            int k = idx >> 5;
            int j = idx & 31;
            s_w4[k * 32 + (j & ~7) + ((j & 7) ^ (k & 7))] = wbase[idx];
        }
    }

#pragma unroll 1
    for (int itg = 0; itg < ITERS_PER_CTA; ++itg) {
        const int nb  = blockIdx.x * GROUPS_PER_CHUNK + itg * 2 + h;
        const int b   = nb / 36;
        const int r   = nb - b * 36;
        const int oh  = r / 3;
        const int ow0 = (r - oh * 3) * GPOS;

        __syncthreads();    // prior iter done with s_x (and itg=0: nothing yet)

        // ---- stage x patch for this half: [kh*6+w][i*32+inc]
        {
            const float* xb = x + (size_t)b * 256 * 14 * 14;
#pragma unroll
            for (int pass = 0; pass < 16; ++pass) {
                int e   = htid + pass * HALF_THR;   // 0..4607
                int c   = e / 18;
                int rr  = e - c * 18;
                int khh = rr / 6;
                int ww  = rr - khh * 6;
                float val = xb[(c * 14 + oh + khh) * 14 + ow0 + ww];
                s_xh[(khh * 6 + ww) * 256 + (c & 7) * 32 + (c >> 3)] = val;
            }
        }
        __syncthreads();    // x ready (also orders weight staging on itg=0)

        // ---- priors: pr[g][c] = sum_i x[g][k][i] * w[o][k][i][c]
        float pr[GPOS][16];
#pragma unroll
        for (int g = 0; g < GPOS; ++g)
#pragma unroll
            for (int c = 0; c < 16; ++c) pr[g][c] = 0.0f;

        const float* sxbase = s_xh + (kh * 6 + kw) * 256 + lane;  // lane==inc
#pragma unroll
        for (int i = 0; i < 8; ++i) {
            float wv[16];
#pragma unroll
            for (int jj = 0; jj < 4; ++jj) {
                int j = i * 4 + jj;
                float4 q = s_w4[htid * 32 + (j & ~7) + ((j & 7) ^ (htid & 7))];
                wv[jj * 4 + 0] = q.x; wv[jj * 4 + 1] = q.y;
                wv[jj * 4 + 2] = q.z; wv[jj * 4 + 3] = q.w;
            }
#pragma unroll
            for (int g = 0; g < GPOS; ++g) {
                float t = sxbase[i * 32 + g * 256];
#pragma unroll
                for (int c = 0; c < 16; ++c) pr[g][c] = fmaf(t, wv[c], pr[g][c]);
            }
        }

        // ---- dynamic routing, each half on its own 4 positions
#pragma unroll 1
        for (int g = 0; g < GPOS; ++g) {
            float logit = 0.0f;
            float scale = 0.0f;

#pragma unroll 1
            for (int it = 0; it < 3; ++it) {
                float p;
                if (it == 0) {
                    p = 1.0f / 288.0f;
                } else {
                    float m = logit;
#pragma unroll
                    for (int off = 16; off; off >>= 1)
                        m = fmaxf(m, __shfl_xor_sync(0xffffffffu, m, off));
                    __syncthreads();
                    if (lane == 0) s_sch[wh] = m;
                    __syncthreads();
                    m = s_sch[0];
#pragma unroll
                    for (int ww = 1; ww < NWARP; ++ww) m = fmaxf(m, s_sch[ww]);

                    float e = __expf(logit - m);
                    float Z = e;
#pragma unroll
                    for (int off = 16; off; off >>= 1)
                        Z += __shfl_xor_sync(0xffffffffu, Z, off);
                    __syncthreads();
                    if (lane == 0) s_sch[wh] = Z;
                    __syncthreads();
                    Z = 0.0f;
#pragma unroll
                    for (int ww = 0; ww < NWARP; ++ww) Z += s_sch[ww];
                    p = __fdividef(e, Z);
                }

                // s[c] = sum_k p_k*pr[k][c] : reduce-scatter butterfly
                float y[16];
#pragma unroll
                for (int c = 0; c < 16; ++c) y[c] = p * pr[g][c];
#pragma unroll
                for (int c = 0; c < 8; ++c) {
                    float snd = (lane & 16) ? y[c] : y[c + 8];
                    float rcv = __shfl_xor_sync(0xffffffffu, snd, 16);
                    y[c] = ((lane & 16) ? y[c + 8] : y[c]) + rcv;
                }
#pragma unroll
                for (int c = 0; c < 4; ++c) {
                    float snd = (lane & 8) ? y[c] : y[c + 4];
                    float rcv = __shfl_xor_sync(0xffffffffu, snd, 8);
                    y[c] = ((lane & 8) ? y[c + 4] : y[c]) + rcv;
                }
#pragma unroll
                for (int c = 0; c < 2; ++c) {
                    float snd = (lane & 4) ? y[c] : y[c + 2];
                    float rcv = __shfl_xor_sync(0xffffffffu, snd, 4);
                    y[c] = ((lane & 4) ? y[c + 2] : y[c]) + rcv;
                }
                {
                    float snd = (lane & 2) ? y[0] : y[1];
                    float rcv = __shfl_xor_sync(0xffffffffu, snd, 2);
                    y[0] = ((lane & 2) ? y[1] : y[0]) + rcv;
                }
                y[0] += __shfl_xor_sync(0xffffffffu, y[0], 1);
                // lane l holds warp-sum of component (l>>1)&15

                __syncthreads();
                if (!(lane & 1)) s_parth[wh * 16 + ((lane >> 1) & 15)] = y[0];
                __syncthreads();
                if (htid < 16) {
                    float a = 0.0f;
#pragma unroll
                    for (int ww = 0; ww < NWARP; ++ww) a += s_parth[ww * 16 + htid];
                    s_redh[htid] = a;
                }
                __syncthreads();

                float sq = 0.0f, d = 0.0f;
#pragma unroll
                for (int c = 0; c < 16; ++c) {
                    float v = s_redh[c];
                    sq = fmaf(v, v, sq);
                    d  = fmaf(pr[g][c], v, d);
                }
                scale = __fdividef(sqrtf(sq), 1.0f + sq);
                if (it < 2) logit += scale * d;
            }

            if (htid < 16) s_outh[htid * GPOS + g] = s_redh[htid] * scale;
            __syncthreads();
        }

        // ---- output: 64 threads per half, 16 rows x 4 contiguous floats
        if (htid < 16 * GPOS) {
            int c = htid >> 2;
            int g = htid & 3;
            out[(((size_t)b * 512 + o * 16 + c) * 12 + oh) * 12 + (ow0 + g)]
                = s_outh[c * GPOS + g];
        }
    }
}

extern "C" void kernel_launch(void* const* d_in, const int* in_sizes, int n_in,
                              void* d_out, int out_size)
{
    const float* x = (const float*)d_in[0];
    const float* w = (const float*)d_in[1];
    if (n_in >= 2 && in_sizes[0] == 32 * 288 * 8 * 16 && in_sizes[1] == 4 * 256 * 14 * 14) {
        x = (const float*)d_in[1];
        w = (const float*)d_in[0];
    }
    const int smem_bytes = (288 * 32 * 4 + 2 * 4608 + 2 * NWARP * 16 + 2 * 16
                            + 2 * NWARP + 2 * 64) * (int)sizeof(float);
    cudaFuncSetAttribute(caps_route_kernel,
                         cudaFuncAttributeMaxDynamicSharedMemorySize, smem_bytes);
    dim3 grid(9, 32);   // (position chunk) x (out capsule)
    caps_route_kernel<<<grid, NTHR, smem_bytes>>>(x, w, (float*)d_out);
}